// round 1
// baseline (speedup 1.0000x reference)
#include <cuda_runtime.h>
#include <cstddef>

#define S_LEN 2048
#define HID   2048
#define NH    16
#define HD    128
#define BATCH 2
#define MROWS (BATCH * S_LEN)

#define QSTR 132
#define KSTR 132
#define VSTR 128
#define ATTN_SMEM ((128 * QSTR + 128 * KSTR + 128 * VSTR) * 4)

// Scratch (allocation-free rule: device globals)
__device__ float g_q [(size_t)MROWS * HID];
__device__ float g_k [(size_t)MROWS * HID];
__device__ float g_v [(size_t)MROWS * HID];
__device__ float g_ao[(size_t)MROWS * HID];

// ---------------------------------------------------------------------------
// NT GEMM: C[m,n] = sum_k A[m,k] * W[n,k] (+ bias[n])
// 128x128 block tile, BK=16, 8x8 per-thread tile, register prefetch.
// ---------------------------------------------------------------------------
__global__ __launch_bounds__(256) void sgemm_nt(
    const float* __restrict__ A, const float* __restrict__ W,
    const float* __restrict__ bias, float* __restrict__ C,
    int N, int K)
{
  __shared__ float As[16][128];
  __shared__ float Ws[16][128];

  const int tid  = threadIdx.x;
  const int tx   = tid & 15;
  const int ty   = tid >> 4;
  const int bm   = blockIdx.y << 7;
  const int bn   = blockIdx.x << 7;
  const int lk   = (tid & 3) << 2;   // k offset within tile: 0,4,8,12
  const int lrow = tid >> 2;         // 0..63

  const float* Ap = A + (size_t)(bm + lrow) * K + lk;
  const float* Wp = W + (size_t)(bn + lrow) * K + lk;

  float4 ra0 = *(const float4*)(Ap);
  float4 ra1 = *(const float4*)(Ap + (size_t)64 * K);
  float4 rw0 = *(const float4*)(Wp);
  float4 rw1 = *(const float4*)(Wp + (size_t)64 * K);

  float acc[8][8];
#pragma unroll
  for (int i = 0; i < 8; i++)
#pragma unroll
    for (int j = 0; j < 8; j++) acc[i][j] = 0.f;

  for (int kt = 0; kt < K; kt += 16) {
    As[lk+0][lrow]    = ra0.x; As[lk+1][lrow]    = ra0.y;
    As[lk+2][lrow]    = ra0.z; As[lk+3][lrow]    = ra0.w;
    As[lk+0][lrow+64] = ra1.x; As[lk+1][lrow+64] = ra1.y;
    As[lk+2][lrow+64] = ra1.z; As[lk+3][lrow+64] = ra1.w;
    Ws[lk+0][lrow]    = rw0.x; Ws[lk+1][lrow]    = rw0.y;
    Ws[lk+2][lrow]    = rw0.z; Ws[lk+3][lrow]    = rw0.w;
    Ws[lk+0][lrow+64] = rw1.x; Ws[lk+1][lrow+64] = rw1.y;
    Ws[lk+2][lrow+64] = rw1.z; Ws[lk+3][lrow+64] = rw1.w;
    __syncthreads();

    if (kt + 16 < K) {  // prefetch next tile into registers
      ra0 = *(const float4*)(Ap + kt + 16);
      ra1 = *(const float4*)(Ap + (size_t)64 * K + kt + 16);
      rw0 = *(const float4*)(Wp + kt + 16);
      rw1 = *(const float4*)(Wp + (size_t)64 * K + kt + 16);
    }

#pragma unroll
    for (int kk = 0; kk < 16; kk++) {
      float4 a0 = *(const float4*)&As[kk][ty << 3];
      float4 a1 = *(const float4*)&As[kk][(ty << 3) + 4];
      float4 w0 = *(const float4*)&Ws[kk][tx << 2];        // cols 4tx..4tx+3
      float4 w1 = *(const float4*)&Ws[kk][64 + (tx << 2)]; // cols 64+4tx..
      float av[8] = {a0.x,a0.y,a0.z,a0.w,a1.x,a1.y,a1.z,a1.w};
      float wv[8] = {w0.x,w0.y,w0.z,w0.w,w1.x,w1.y,w1.z,w1.w};
#pragma unroll
      for (int i = 0; i < 8; i++)
#pragma unroll
        for (int j = 0; j < 8; j++)
          acc[i][j] = fmaf(av[i], wv[j], acc[i][j]);
    }
    __syncthreads();
  }

#pragma unroll
  for (int i = 0; i < 8; i++) {
    const int row = bm + (ty << 3) + i;
    float* cp = C + (size_t)row * N + bn;
    float4 o0, o1;
    if (bias) {
      const float* b0 = bias + bn + (tx << 2);
      const float* b1 = bias + bn + 64 + (tx << 2);
      o0.x = acc[i][0] + b0[0]; o0.y = acc[i][1] + b0[1];
      o0.z = acc[i][2] + b0[2]; o0.w = acc[i][3] + b0[3];
      o1.x = acc[i][4] + b1[0]; o1.y = acc[i][5] + b1[1];
      o1.z = acc[i][6] + b1[2]; o1.w = acc[i][7] + b1[3];
    } else {
      o0.x = acc[i][0]; o0.y = acc[i][1]; o0.z = acc[i][2]; o0.w = acc[i][3];
      o1.x = acc[i][4]; o1.y = acc[i][5]; o1.z = acc[i][6]; o1.w = acc[i][7];
    }
    *(float4*)(cp + (tx << 2))      = o0;
    *(float4*)(cp + 64 + (tx << 2)) = o1;
  }
}

// ---------------------------------------------------------------------------
// RoPE (in place on Q and K, layout [b, s, h, d] == [MROWS, HID] row-major)
// ---------------------------------------------------------------------------
__global__ void rope_kernel(float* __restrict__ q, float* __restrict__ k,
                            const float* __restrict__ cosb,
                            const float* __restrict__ sinb)
{
  int i = blockIdx.x * blockDim.x + threadIdx.x;  // over MROWS*NH*64
  int d  = i & 63;
  int h  = (i >> 6) & 15;
  int ms = i >> 10;               // b*S + s
  int s  = ms & (S_LEN - 1);
  size_t base = (size_t)ms * HID + (size_t)h * HD;

  float c1 = cosb[s * HD + d],      s1 = sinb[s * HD + d];
  float c2 = cosb[s * HD + d + 64], s2 = sinb[s * HD + d + 64];

  float q1 = q[base + d], q2 = q[base + d + 64];
  q[base + d]      = q1 * c1 - q2 * s1;
  q[base + d + 64] = q2 * c2 + q1 * s2;

  float k1 = k[base + d], k2 = k[base + d + 64];
  k[base + d]      = k1 * c1 - k2 * s1;
  k[base + d + 64] = k2 * c2 + k1 * s2;
}

// ---------------------------------------------------------------------------
// Flash attention, fp32. 128 q-rows x 128 kv-rows per tile, 256 threads.
// Thread (tx,ty): score rows 8*ty+i, score cols tx+16*j; O cols {4tx,64+4tx}.
// P staged transposed in the K smem buffer for a conflict-free PV loop.
// ---------------------------------------------------------------------------
__global__ __launch_bounds__(256, 1) void attn_kernel(
    const float* __restrict__ Q, const float* __restrict__ K,
    const float* __restrict__ V, float* __restrict__ O)
{
  extern __shared__ float sm[];
  float* Qs = sm;                         // [128][QSTR]
  float* Ks = sm + 128 * QSTR;            // [128][KSTR], reused as P^T
  float* Vs = sm + 128 * (QSTR + KSTR);   // [128][VSTR]

  const int tid = threadIdx.x;
  const int tx  = tid & 15;
  const int ty  = tid >> 4;
  const int q0  = blockIdx.x << 7;
  const int b   = blockIdx.y >> 4;
  const int h   = blockIdx.y & 15;
  const size_t boff = (size_t)b * S_LEN * HID + (size_t)h * HD;
  const float* Qb = Q + boff;
  const float* Kb = K + boff;
  const float* Vb = V + boff;
  float*       Ob = O + boff;

  const float scale = 0.08838834764831845f;  // 1/sqrt(128)

  // Load Q tile (pre-scaled)
#pragma unroll
  for (int it = 0; it < 16; it++) {
    int f = tid + (it << 8);
    int row = f >> 5;
    int c = (f & 31) << 2;
    float4 v = *(const float4*)&Qb[(size_t)(q0 + row) * HID + c];
    v.x *= scale; v.y *= scale; v.z *= scale; v.w *= scale;
    *(float4*)&Qs[row * QSTR + c] = v;
  }

  float m_i[8], l_i[8], acc[8][8];
#pragma unroll
  for (int i = 0; i < 8; i++) {
    m_i[i] = -1e30f; l_i[i] = 0.f;
#pragma unroll
    for (int c = 0; c < 8; c++) acc[i][c] = 0.f;
  }

  for (int kt = 0; kt < S_LEN / 128; kt++) {
    const int k0 = kt << 7;
    __syncthreads();  // previous PV done (and Q load visible on iter 0)
#pragma unroll
    for (int it = 0; it < 16; it++) {
      int f = tid + (it << 8);
      int row = f >> 5;
      int c = (f & 31) << 2;
      *(float4*)&Ks[row * KSTR + c] = *(const float4*)&Kb[(size_t)(k0 + row) * HID + c];
      *(float4*)&Vs[row * VSTR + c] = *(const float4*)&Vb[(size_t)(k0 + row) * HID + c];
    }
    __syncthreads();

    // S = Q K^T (pre-scaled)
    float sf[8][8];
#pragma unroll
    for (int i = 0; i < 8; i++)
#pragma unroll
      for (int j = 0; j < 8; j++) sf[i][j] = 0.f;

#pragma unroll 4
    for (int d4 = 0; d4 < 32; d4++) {
      float4 bb[8];
#pragma unroll
      for (int j = 0; j < 8; j++)
        bb[j] = *(const float4*)&Ks[(tx + (j << 4)) * KSTR + (d4 << 2)];
#pragma unroll
      for (int i = 0; i < 8; i++) {
        float4 a = *(const float4*)&Qs[((ty << 3) + i) * QSTR + (d4 << 2)];
#pragma unroll
        for (int j = 0; j < 8; j++) {
          sf[i][j] = fmaf(a.x, bb[j].x, sf[i][j]);
          sf[i][j] = fmaf(a.y, bb[j].y, sf[i][j]);
          sf[i][j] = fmaf(a.z, bb[j].z, sf[i][j]);
          sf[i][j] = fmaf(a.w, bb[j].w, sf[i][j]);
        }
      }
    }

    // online softmax (row reduction across the 16 tx lanes, width-16 shuffles)
#pragma unroll
    for (int i = 0; i < 8; i++) {
      float rm = sf[i][0];
#pragma unroll
      for (int j = 1; j < 8; j++) rm = fmaxf(rm, sf[i][j]);
#pragma unroll
      for (int o = 8; o > 0; o >>= 1)
        rm = fmaxf(rm, __shfl_xor_sync(0xffffffffu, rm, o));
      float mnew = fmaxf(m_i[i], rm);
      float fac  = __expf(m_i[i] - mnew);
      m_i[i] = mnew;
      float rs = 0.f;
#pragma unroll
      for (int j = 0; j < 8; j++) {
        float p = __expf(sf[i][j] - mnew);
        sf[i][j] = p;
        rs += p;
      }
#pragma unroll
      for (int o = 8; o > 0; o >>= 1)
        rs += __shfl_xor_sync(0xffffffffu, rs, o);
      l_i[i] = l_i[i] * fac + rs;
#pragma unroll
      for (int c = 0; c < 8; c++) acc[i][c] *= fac;
    }

    __syncthreads();  // all threads done reading Ks
    // stage P transposed into Ks buffer: Pt[kv_col][q_row]
#pragma unroll
    for (int i = 0; i < 8; i++)
#pragma unroll
      for (int j = 0; j < 8; j++)
        Ks[(tx + (j << 4)) * KSTR + (ty << 3) + i] = sf[i][j];
    __syncthreads();

    // O += P V
#pragma unroll 2
    for (int j = 0; j < 128; j++) {
      float4 p0 = *(const float4*)&Ks[j * KSTR + (ty << 3)];
      float4 p1 = *(const float4*)&Ks[j * KSTR + (ty << 3) + 4];
      float4 v0 = *(const float4*)&Vs[j * VSTR + (tx << 2)];
      float4 v1 = *(const float4*)&Vs[j * VSTR + 64 + (tx << 2)];
      float pv[8] = {p0.x,p0.y,p0.z,p0.w,p1.x,p1.y,p1.z,p1.w};
      float vv[8] = {v0.x,v0.y,v0.z,v0.w,v1.x,v1.y,v1.z,v1.w};
#pragma unroll
      for (int i = 0; i < 8; i++)
#pragma unroll
        for (int c = 0; c < 8; c++)
          acc[i][c] = fmaf(pv[i], vv[c], acc[i][c]);
    }
  }

  // epilogue
#pragma unroll
  for (int i = 0; i < 8; i++) {
    const float inv = 1.f / l_i[i];
    const int row = q0 + (ty << 3) + i;
    float* op = Ob + (size_t)row * HID;
    float4 o0, o1;
    o0.x = acc[i][0]*inv; o0.y = acc[i][1]*inv; o0.z = acc[i][2]*inv; o0.w = acc[i][3]*inv;
    o1.x = acc[i][4]*inv; o1.y = acc[i][5]*inv; o1.z = acc[i][6]*inv; o1.w = acc[i][7]*inv;
    *(float4*)(op + (tx << 2))      = o0;
    *(float4*)(op + 64 + (tx << 2)) = o1;
  }
}

// ---------------------------------------------------------------------------
extern "C" void kernel_launch(void* const* d_in, const int* in_sizes, int n_in,
                              void* d_out, int out_size)
{
  (void)in_sizes; (void)n_in; (void)out_size;
  const float* x    = (const float*)d_in[0];
  const float* cosb = (const float*)d_in[1];
  const float* sinb = (const float*)d_in[2];
  const float* wq   = (const float*)d_in[3];
  const float* bq   = (const float*)d_in[4];
  const float* wk   = (const float*)d_in[5];
  const float* bk   = (const float*)d_in[6];
  const float* wv   = (const float*)d_in[7];
  const float* bv   = (const float*)d_in[8];
  const float* wo   = (const float*)d_in[9];
  float* out = (float*)d_out;

  float *q, *k, *v, *ao;
  cudaGetSymbolAddress((void**)&q,  g_q);
  cudaGetSymbolAddress((void**)&k,  g_k);
  cudaGetSymbolAddress((void**)&v,  g_v);
  cudaGetSymbolAddress((void**)&ao, g_ao);

  cudaFuncSetAttribute(attn_kernel,
                       cudaFuncAttributeMaxDynamicSharedMemorySize, ATTN_SMEM);

  dim3 gg(HID / 128, MROWS / 128);
  sgemm_nt<<<gg, 256>>>(x,  wq, bq, q,  HID, HID);
  sgemm_nt<<<gg, 256>>>(x,  wk, bk, k,  HID, HID);
  sgemm_nt<<<gg, 256>>>(x,  wv, bv, v,  HID, HID);

  rope_kernel<<<(MROWS * NH * 64) / 256, 256>>>(q, k, cosb, sinb);

  attn_kernel<<<dim3(S_LEN / 128, BATCH * NH), 256, ATTN_SMEM>>>(q, k, v, ao);

  sgemm_nt<<<gg, 256>>>(ao, wo, nullptr, out, HID, HID);
}

// round 3
// speedup vs baseline: 1.5264x; 1.5264x over previous
#include <cuda_runtime.h>
#include <cuda_bf16.h>
#include <cstdint>
#include <cstddef>

#define S_LEN 2048
#define HID   2048
#define NH    16
#define HD    128
#define BATCH 2
#define MROWS (BATCH * S_LEN)

#define QSTR 132
#define KSTR 132
#define VSTR 128
#define ATTN_SMEM ((128 * QSTR + 128 * KSTR + 128 * VSTR) * 4)

// ---------------------------------------------------------------------------
// Scratch (allocation-free rule: device globals)
// ---------------------------------------------------------------------------
__device__ float g_q [(size_t)MROWS * HID];
__device__ float g_k [(size_t)MROWS * HID];
__device__ float g_v [(size_t)MROWS * HID];
__device__ float g_ao[(size_t)MROWS * HID];

__device__ __nv_bfloat16 g_xhi[(size_t)MROWS * HID];
__device__ __nv_bfloat16 g_xlo[(size_t)MROWS * HID];
__device__ __nv_bfloat16 g_whi[4][(size_t)HID * HID];
__device__ __nv_bfloat16 g_wlo[4][(size_t)HID * HID];
__device__ __nv_bfloat16 g_aohi[(size_t)MROWS * HID];
__device__ __nv_bfloat16 g_aolo[(size_t)MROWS * HID];

// ---------------------------------------------------------------------------
// helpers
// ---------------------------------------------------------------------------
__device__ __forceinline__ uint32_t smem_u32(const void* p) {
  uint32_t a;
  asm("{ .reg .u64 t; cvta.to.shared.u64 t, %1; cvt.u32.u64 %0, t; }"
      : "=r"(a) : "l"(p));
  return a;
}

__device__ __forceinline__ void ldsm4(uint32_t addr, uint32_t& r0, uint32_t& r1,
                                      uint32_t& r2, uint32_t& r3) {
  asm volatile("ldmatrix.sync.aligned.m8n8.x4.shared.b16 {%0,%1,%2,%3}, [%4];"
               : "=r"(r0), "=r"(r1), "=r"(r2), "=r"(r3) : "r"(addr));
}

__device__ __forceinline__ void mma16816(float* d, const uint32_t* a,
                                         const uint32_t* b) {
  asm volatile(
      "mma.sync.aligned.m16n8k16.row.col.f32.bf16.bf16.f32 "
      "{%0,%1,%2,%3}, {%4,%5,%6,%7}, {%8,%9}, {%0,%1,%2,%3};"
      : "+f"(d[0]), "+f"(d[1]), "+f"(d[2]), "+f"(d[3])
      : "r"(a[0]), "r"(a[1]), "r"(a[2]), "r"(a[3]), "r"(b[0]), "r"(b[1]));
}

#define CP_ASYNC16(saddr, gaddr) \
  asm volatile("cp.async.cg.shared.global [%0], [%1], 16;" \
               :: "r"(saddr), "l"(gaddr))
#define CP_COMMIT() asm volatile("cp.async.commit_group;")
#define CP_WAIT1()  asm volatile("cp.async.wait_group 1;")
#define CP_WAIT0()  asm volatile("cp.async.wait_group 0;")

// ---------------------------------------------------------------------------
// fp32 -> bf16 hi/lo split
// ---------------------------------------------------------------------------
__global__ void cvt_split(const float* __restrict__ in,
                          __nv_bfloat16* __restrict__ hi,
                          __nv_bfloat16* __restrict__ lo, int n) {
  int i = (blockIdx.x * blockDim.x + threadIdx.x) * 4;
  if (i >= n) return;
  float4 v = *(const float4*)(in + i);
  __nv_bfloat16 h0 = __float2bfloat16_rn(v.x);
  __nv_bfloat16 h1 = __float2bfloat16_rn(v.y);
  __nv_bfloat16 h2 = __float2bfloat16_rn(v.z);
  __nv_bfloat16 h3 = __float2bfloat16_rn(v.w);
  __nv_bfloat16 l0 = __float2bfloat16_rn(v.x - __bfloat162float(h0));
  __nv_bfloat16 l1 = __float2bfloat16_rn(v.y - __bfloat162float(h1));
  __nv_bfloat16 l2 = __float2bfloat16_rn(v.z - __bfloat162float(h2));
  __nv_bfloat16 l3 = __float2bfloat16_rn(v.w - __bfloat162float(h3));
  union { __nv_bfloat16 b[4]; uint2 u; } H, L;
  H.b[0] = h0; H.b[1] = h1; H.b[2] = h2; H.b[3] = h3;
  L.b[0] = l0; L.b[1] = l1; L.b[2] = l2; L.b[3] = l3;
  *(uint2*)(hi + i) = H.u;
  *(uint2*)(lo + i) = L.u;
}

// ---------------------------------------------------------------------------
// HMMA bf16x3 GEMM: C[m,n] = sum_k A[m,k]*W[n,k] (+ bias[n])
// M=4096, N=2048, K=2048. CTA 128x128, BK=32, 8 warps of 64x32.
// smem tiles: [128 rows][40 bf16] (80B stride: 16B aligned, ldmatrix
// conflict-free since 20*r mod 32 is distinct over any 8-row phase).
// ---------------------------------------------------------------------------
#define BK 32
#define NCHUNK (HID / BK)        // 64
#define TSTR 40                  // bf16 elems per smem row
#define TELEM (128 * TSTR)       // 5120 elems per tile
#define BUFELEM (4 * TELEM)      // Ahi, Alo, Bhi, Blo
#define GEMM_SMEM (2 * BUFELEM * 2)  // bytes = 81920

__global__ __launch_bounds__(256, 1) void gemm_mma_bf16x3(
    const __nv_bfloat16* __restrict__ Ahi, const __nv_bfloat16* __restrict__ Alo,
    const __nv_bfloat16* __restrict__ Bhi, const __nv_bfloat16* __restrict__ Blo,
    const float* __restrict__ bias, float* __restrict__ C) {
  extern __shared__ __nv_bfloat16 smb[];
  const uint32_t sbase = smem_u32(smb);
  const int tid  = threadIdx.x;
  const int wid  = tid >> 5;
  const int lane = tid & 31;
  const int bm = blockIdx.y << 7;
  const int bn = blockIdx.x << 7;
  const int warp_m = (wid & 1) << 6;   // 0 or 64
  const int warp_n = (wid >> 1) << 5;  // 0,32,64,96

  const __nv_bfloat16* gp[4] = {
      Ahi + (size_t)bm * HID, Alo + (size_t)bm * HID,
      Bhi + (size_t)bn * HID, Blo + (size_t)bn * HID};

  // per-thread load slots: row = u>>2, col-block = (u&3)*8 (bf16)
  const int lrow = 0;  (void)lrow;

  auto issue_chunk = [&](int c) {
    const int p = c & 1;
    const int k0 = c * BK;
    const uint32_t s0 = sbase + p * BUFELEM * 2;
#pragma unroll
    for (int t = 0; t < 4; t++) {
#pragma unroll
      for (int i = 0; i < 2; i++) {
        int u = tid + (i << 8);
        int row = u >> 2;
        int cc = (u & 3) << 3;
        const __nv_bfloat16* ga = gp[t] + (size_t)row * HID + k0 + cc;
        uint32_t sa = s0 + (t * TELEM + row * TSTR + cc) * 2;
        CP_ASYNC16(sa, ga);
      }
    }
    CP_COMMIT();
  };

  float acc[4][4][4];
#pragma unroll
  for (int mt = 0; mt < 4; mt++)
#pragma unroll
    for (int nt = 0; nt < 4; nt++)
#pragma unroll
      for (int r = 0; r < 4; r++) acc[mt][nt][r] = 0.f;

  issue_chunk(0);

  for (int c = 0; c < NCHUNK; c++) {
    if (c + 1 < NCHUNK) { issue_chunk(c + 1); CP_WAIT1(); }
    else                { CP_WAIT0(); }
    __syncthreads();

    const uint32_t buf = sbase + (c & 1) * BUFELEM * 2;
    const uint32_t aHi = buf;
    const uint32_t aLo = buf + TELEM * 2;
    const uint32_t bHi = buf + 2 * TELEM * 2;
    const uint32_t bLo = buf + 3 * TELEM * 2;

#pragma unroll
    for (int ks = 0; ks < 2; ks++) {
      const int kc = ks << 4;
      // A fragments (hi & lo): row = warp_m + mt*16 + (lane&15), k = kc + (lane>>4)*8
      uint32_t ah[4][4], al[4][4];
      const int arow = warp_m + (lane & 15);
      const int acol = kc + ((lane >> 4) << 3);
#pragma unroll
      for (int mt = 0; mt < 4; mt++) {
        uint32_t off = ((arow + (mt << 4)) * TSTR + acol) * 2;
        ldsm4(aHi + off, ah[mt][0], ah[mt][1], ah[mt][2], ah[mt][3]);
        ldsm4(aLo + off, al[mt][0], al[mt][1], al[mt][2], al[mt][3]);
      }
      // B fragments: one x4 covers two n-tiles (both k halves)
      uint32_t bh[4][2], bl[4][2];
      const int brow0 = (lane & 7) + ((lane >> 4) << 3);  // + nbase
      const int bcol  = kc + (((lane >> 3) & 1) << 3);
#pragma unroll
      for (int pr = 0; pr < 2; pr++) {
        const int nb = warp_n + (pr << 4);
        uint32_t off = ((nb + brow0) * TSTR + bcol) * 2;
        ldsm4(bHi + off, bh[pr*2][0], bh[pr*2][1], bh[pr*2+1][0], bh[pr*2+1][1]);
        ldsm4(bLo + off, bl[pr*2][0], bl[pr*2][1], bl[pr*2+1][0], bl[pr*2+1][1]);
      }
#pragma unroll
      for (int mt = 0; mt < 4; mt++)
#pragma unroll
        for (int nt = 0; nt < 4; nt++) {
          mma16816(acc[mt][nt], ah[mt], bh[nt]);
          mma16816(acc[mt][nt], ah[mt], bl[nt]);
          mma16816(acc[mt][nt], al[mt], bh[nt]);
        }
    }
    __syncthreads();
  }

  // epilogue: accum layout r = lane>>2, c = (lane&3)*2
  const int r  = lane >> 2;
  const int c2 = (lane & 3) << 1;
#pragma unroll
  for (int mt = 0; mt < 4; mt++) {
    const int row0 = bm + warp_m + (mt << 4) + r;
#pragma unroll
    for (int nt = 0; nt < 4; nt++) {
      const int col = bn + warp_n + (nt << 3) + c2;
      float b0 = 0.f, b1 = 0.f;
      if (bias) { b0 = bias[col]; b1 = bias[col + 1]; }
      float2 v0 = {acc[mt][nt][0] + b0, acc[mt][nt][1] + b1};
      float2 v1 = {acc[mt][nt][2] + b0, acc[mt][nt][3] + b1};
      *(float2*)&C[(size_t)row0 * HID + col]       = v0;
      *(float2*)&C[(size_t)(row0 + 8) * HID + col] = v1;
    }
  }
}

// ---------------------------------------------------------------------------
// RoPE (in place on Q and K)
// ---------------------------------------------------------------------------
__global__ void rope_kernel(float* __restrict__ q, float* __restrict__ k,
                            const float* __restrict__ cosb,
                            const float* __restrict__ sinb)
{
  int i = blockIdx.x * blockDim.x + threadIdx.x;
  int d  = i & 63;
  int h  = (i >> 6) & 15;
  int ms = i >> 10;
  int s  = ms & (S_LEN - 1);
  size_t base = (size_t)ms * HID + (size_t)h * HD;

  float c1 = cosb[s * HD + d],      s1 = sinb[s * HD + d];
  float c2 = cosb[s * HD + d + 64], s2 = sinb[s * HD + d + 64];

  float q1 = q[base + d], q2 = q[base + d + 64];
  q[base + d]      = q1 * c1 - q2 * s1;
  q[base + d + 64] = q2 * c2 + q1 * s2;

  float k1 = k[base + d], k2 = k[base + d + 64];
  k[base + d]      = k1 * c1 - k2 * s1;
  k[base + d + 64] = k2 * c2 + k1 * s2;
}

// ---------------------------------------------------------------------------
// Flash attention, fp32 SIMT (unchanged, passing)
// ---------------------------------------------------------------------------
__global__ __launch_bounds__(256, 1) void attn_kernel(
    const float* __restrict__ Q, const float* __restrict__ K,
    const float* __restrict__ V, float* __restrict__ O)
{
  extern __shared__ float sm[];
  float* Qs = sm;
  float* Ks = sm + 128 * QSTR;
  float* Vs = sm + 128 * (QSTR + KSTR);

  const int tid = threadIdx.x;
  const int tx  = tid & 15;
  const int ty  = tid >> 4;
  const int q0  = blockIdx.x << 7;
  const int b   = blockIdx.y >> 4;
  const int h   = blockIdx.y & 15;
  const size_t boff = (size_t)b * S_LEN * HID + (size_t)h * HD;
  const float* Qb = Q + boff;
  const float* Kb = K + boff;
  const float* Vb = V + boff;
  float*       Ob = O + boff;

  const float scale = 0.08838834764831845f;

#pragma unroll
  for (int it = 0; it < 16; it++) {
    int f = tid + (it << 8);
    int row = f >> 5;
    int c = (f & 31) << 2;
    float4 v = *(const float4*)&Qb[(size_t)(q0 + row) * HID + c];
    v.x *= scale; v.y *= scale; v.z *= scale; v.w *= scale;
    *(float4*)&Qs[row * QSTR + c] = v;
  }

  float m_i[8], l_i[8], acc[8][8];
#pragma unroll
  for (int i = 0; i < 8; i++) {
    m_i[i] = -1e30f; l_i[i] = 0.f;
#pragma unroll
    for (int c = 0; c < 8; c++) acc[i][c] = 0.f;
  }

  for (int kt = 0; kt < S_LEN / 128; kt++) {
    const int k0 = kt << 7;
    __syncthreads();
#pragma unroll
    for (int it = 0; it < 16; it++) {
      int f = tid + (it << 8);
      int row = f >> 5;
      int c = (f & 31) << 2;
      *(float4*)&Ks[row * KSTR + c] = *(const float4*)&Kb[(size_t)(k0 + row) * HID + c];
      *(float4*)&Vs[row * VSTR + c] = *(const float4*)&Vb[(size_t)(k0 + row) * HID + c];
    }
    __syncthreads();

    float sf[8][8];
#pragma unroll
    for (int i = 0; i < 8; i++)
#pragma unroll
      for (int j = 0; j < 8; j++) sf[i][j] = 0.f;

#pragma unroll 4
    for (int d4 = 0; d4 < 32; d4++) {
      float4 bb[8];
#pragma unroll
      for (int j = 0; j < 8; j++)
        bb[j] = *(const float4*)&Ks[(tx + (j << 4)) * KSTR + (d4 << 2)];
#pragma unroll
      for (int i = 0; i < 8; i++) {
        float4 a = *(const float4*)&Qs[((ty << 3) + i) * QSTR + (d4 << 2)];
#pragma unroll
        for (int j = 0; j < 8; j++) {
          sf[i][j] = fmaf(a.x, bb[j].x, sf[i][j]);
          sf[i][j] = fmaf(a.y, bb[j].y, sf[i][j]);
          sf[i][j] = fmaf(a.z, bb[j].z, sf[i][j]);
          sf[i][j] = fmaf(a.w, bb[j].w, sf[i][j]);
        }
      }
    }

#pragma unroll
    for (int i = 0; i < 8; i++) {
      float rm = sf[i][0];
#pragma unroll
      for (int j = 1; j < 8; j++) rm = fmaxf(rm, sf[i][j]);
#pragma unroll
      for (int o = 8; o > 0; o >>= 1)
        rm = fmaxf(rm, __shfl_xor_sync(0xffffffffu, rm, o));
      float mnew = fmaxf(m_i[i], rm);
      float fac  = __expf(m_i[i] - mnew);
      m_i[i] = mnew;
      float rs = 0.f;
#pragma unroll
      for (int j = 0; j < 8; j++) {
        float p = __expf(sf[i][j] - mnew);
        sf[i][j] = p;
        rs += p;
      }
#pragma unroll
      for (int o = 8; o > 0; o >>= 1)
        rs += __shfl_xor_sync(0xffffffffu, rs, o);
      l_i[i] = l_i[i] * fac + rs;
#pragma unroll
      for (int c = 0; c < 8; c++) acc[i][c] *= fac;
    }

    __syncthreads();
#pragma unroll
    for (int i = 0; i < 8; i++)
#pragma unroll
      for (int j = 0; j < 8; j++)
        Ks[(tx + (j << 4)) * KSTR + (ty << 3) + i] = sf[i][j];
    __syncthreads();

#pragma unroll 2
    for (int j = 0; j < 128; j++) {
      float4 p0 = *(const float4*)&Ks[j * KSTR + (ty << 3)];
      float4 p1 = *(const float4*)&Ks[j * KSTR + (ty << 3) + 4];
      float4 v0 = *(const float4*)&Vs[j * VSTR + (tx << 2)];
      float4 v1 = *(const float4*)&Vs[j * VSTR + 64 + (tx << 2)];
      float pv[8] = {p0.x,p0.y,p0.z,p0.w,p1.x,p1.y,p1.z,p1.w};
      float vv[8] = {v0.x,v0.y,v0.z,v0.w,v1.x,v1.y,v1.z,v1.w};
#pragma unroll
      for (int i = 0; i < 8; i++)
#pragma unroll
        for (int c = 0; c < 8; c++)
          acc[i][c] = fmaf(pv[i], vv[c], acc[i][c]);
    }
  }

#pragma unroll
  for (int i = 0; i < 8; i++) {
    const float inv = 1.f / l_i[i];
    const int row = q0 + (ty << 3) + i;
    float* op = Ob + (size_t)row * HID;
    float4 o0, o1;
    o0.x = acc[i][0]*inv; o0.y = acc[i][1]*inv; o0.z = acc[i][2]*inv; o0.w = acc[i][3]*inv;
    o1.x = acc[i][4]*inv; o1.y = acc[i][5]*inv; o1.z = acc[i][6]*inv; o1.w = acc[i][7]*inv;
    *(float4*)(op + (tx << 2))      = o0;
    *(float4*)(op + 64 + (tx << 2)) = o1;
  }
}

// ---------------------------------------------------------------------------
extern "C" void kernel_launch(void* const* d_in, const int* in_sizes, int n_in,
                              void* d_out, int out_size)
{
  (void)in_sizes; (void)n_in; (void)out_size;
  const float* x    = (const float*)d_in[0];
  const float* cosb = (const float*)d_in[1];
  const float* sinb = (const float*)d_in[2];
  const float* wq   = (const float*)d_in[3];
  const float* bq   = (const float*)d_in[4];
  const float* wk   = (const float*)d_in[5];
  const float* bk   = (const float*)d_in[6];
  const float* wv   = (const float*)d_in[7];
  const float* bv   = (const float*)d_in[8];
  const float* wo   = (const float*)d_in[9];
  float* out = (float*)d_out;

  float *q, *k, *v, *ao;
  cudaGetSymbolAddress((void**)&q,  g_q);
  cudaGetSymbolAddress((void**)&k,  g_k);
  cudaGetSymbolAddress((void**)&v,  g_v);
  cudaGetSymbolAddress((void**)&ao, g_ao);

  __nv_bfloat16 *xhi, *xlo, *whi, *wlo, *aohi, *aolo;
  cudaGetSymbolAddress((void**)&xhi,  g_xhi);
  cudaGetSymbolAddress((void**)&xlo,  g_xlo);
  cudaGetSymbolAddress((void**)&whi,  g_whi);
  cudaGetSymbolAddress((void**)&wlo,  g_wlo);
  cudaGetSymbolAddress((void**)&aohi, g_aohi);
  cudaGetSymbolAddress((void**)&aolo, g_aolo);

  static bool attrs_set = false;
  if (!attrs_set) {
    cudaFuncSetAttribute(attn_kernel,
                         cudaFuncAttributeMaxDynamicSharedMemorySize, ATTN_SMEM);
    cudaFuncSetAttribute(gemm_mma_bf16x3,
                         cudaFuncAttributeMaxDynamicSharedMemorySize, GEMM_SMEM);
    attrs_set = true;
  }

  const int NX = MROWS * HID;
  const int NW = HID * HID;
  const size_t WSTRIDE = (size_t)HID * HID;

  cvt_split<<<NX / 1024, 256>>>(x,  xhi, xlo, NX);
  cvt_split<<<NW / 1024, 256>>>(wq, whi + 0 * WSTRIDE, wlo + 0 * WSTRIDE, NW);
  cvt_split<<<NW / 1024, 256>>>(wk, whi + 1 * WSTRIDE, wlo + 1 * WSTRIDE, NW);
  cvt_split<<<NW / 1024, 256>>>(wv, whi + 2 * WSTRIDE, wlo + 2 * WSTRIDE, NW);
  cvt_split<<<NW / 1024, 256>>>(wo, whi + 3 * WSTRIDE, wlo + 3 * WSTRIDE, NW);

  dim3 gg(HID / 128, MROWS / 128);  // (16, 32)
  gemm_mma_bf16x3<<<gg, 256, GEMM_SMEM>>>(xhi, xlo, whi + 0 * WSTRIDE, wlo + 0 * WSTRIDE, bq, q);
  gemm_mma_bf16x3<<<gg, 256, GEMM_SMEM>>>(xhi, xlo, whi + 1 * WSTRIDE, wlo + 1 * WSTRIDE, bk, k);
  gemm_mma_bf16x3<<<gg, 256, GEMM_SMEM>>>(xhi, xlo, whi + 2 * WSTRIDE, wlo + 2 * WSTRIDE, bv, v);

  rope_kernel<<<(MROWS * NH * 64) / 256, 256>>>(q, k, cosb, sinb);

  attn_kernel<<<dim3(S_LEN / 128, BATCH * NH), 256, ATTN_SMEM>>>(q, k, v, ao);

  cvt_split<<<NX / 1024, 256>>>(ao, aohi, aolo, NX);
  gemm_mma_bf16x3<<<gg, 256, GEMM_SMEM>>>(aohi, aolo, whi + 3 * WSTRIDE, wlo + 3 * WSTRIDE, nullptr, out);
}

// round 4
// speedup vs baseline: 2.2912x; 1.5011x over previous
#include <cuda_runtime.h>
#include <cuda_bf16.h>
#include <cstdint>
#include <cstddef>

#define S_LEN 2048
#define HID   2048
#define NH    16
#define HD    128
#define BATCH 2
#define MROWS (BATCH * S_LEN)

// ---------------------------------------------------------------------------
// Scratch (allocation-free rule: device globals)
// ---------------------------------------------------------------------------
__device__ float g_q [(size_t)MROWS * HID];
__device__ float g_k [(size_t)MROWS * HID];
__device__ float g_v [(size_t)MROWS * HID];
__device__ float g_ao[(size_t)MROWS * HID];

__device__ __nv_bfloat16 g_xhi[(size_t)MROWS * HID];
__device__ __nv_bfloat16 g_xlo[(size_t)MROWS * HID];
__device__ __nv_bfloat16 g_whi[4][(size_t)HID * HID];
__device__ __nv_bfloat16 g_wlo[4][(size_t)HID * HID];
__device__ __nv_bfloat16 g_aohi[(size_t)MROWS * HID];
__device__ __nv_bfloat16 g_aolo[(size_t)MROWS * HID];

__device__ __nv_bfloat16 g_qhi[(size_t)MROWS * HID];
__device__ __nv_bfloat16 g_qlo[(size_t)MROWS * HID];
__device__ __nv_bfloat16 g_khi[(size_t)MROWS * HID];
__device__ __nv_bfloat16 g_klo[(size_t)MROWS * HID];
__device__ __nv_bfloat16 g_vhi[(size_t)MROWS * HID];
__device__ __nv_bfloat16 g_vlo[(size_t)MROWS * HID];

// ---------------------------------------------------------------------------
// helpers
// ---------------------------------------------------------------------------
__device__ __forceinline__ uint32_t smem_u32(const void* p) {
  uint32_t a;
  asm("{ .reg .u64 t; cvta.to.shared.u64 t, %1; cvt.u32.u64 %0, t; }"
      : "=r"(a) : "l"(p));
  return a;
}

__device__ __forceinline__ void ldsm4(uint32_t addr, uint32_t& r0, uint32_t& r1,
                                      uint32_t& r2, uint32_t& r3) {
  asm volatile("ldmatrix.sync.aligned.m8n8.x4.shared.b16 {%0,%1,%2,%3}, [%4];"
               : "=r"(r0), "=r"(r1), "=r"(r2), "=r"(r3) : "r"(addr));
}

__device__ __forceinline__ void ldsm4t(uint32_t addr, uint32_t& r0, uint32_t& r1,
                                       uint32_t& r2, uint32_t& r3) {
  asm volatile("ldmatrix.sync.aligned.m8n8.x4.trans.shared.b16 {%0,%1,%2,%3}, [%4];"
               : "=r"(r0), "=r"(r1), "=r"(r2), "=r"(r3) : "r"(addr));
}

__device__ __forceinline__ void mma16816(float* d, const uint32_t* a,
                                         const uint32_t* b) {
  asm volatile(
      "mma.sync.aligned.m16n8k16.row.col.f32.bf16.bf16.f32 "
      "{%0,%1,%2,%3}, {%4,%5,%6,%7}, {%8,%9}, {%0,%1,%2,%3};"
      : "+f"(d[0]), "+f"(d[1]), "+f"(d[2]), "+f"(d[3])
      : "r"(a[0]), "r"(a[1]), "r"(a[2]), "r"(a[3]), "r"(b[0]), "r"(b[1]));
}

#define CP_ASYNC16(saddr, gaddr) \
  asm volatile("cp.async.cg.shared.global [%0], [%1], 16;" \
               :: "r"(saddr), "l"(gaddr))
#define CP_COMMIT() asm volatile("cp.async.commit_group;")
#define CP_WAIT1()  asm volatile("cp.async.wait_group 1;")
#define CP_WAIT0()  asm volatile("cp.async.wait_group 0;")

// FFMA-only exp2 (no MUFU): magic-round + degree-6 Taylor, |err| < 2e-7.
__device__ __forceinline__ float exp2p(float x) {
  x = fmaxf(x, -126.f);
  float r = x + 12582912.f;                 // round-to-nearest int in low bits
  int   e = __float_as_int(r) - 0x4B400000; // n as integer
  float f = x - (r - 12582912.f);           // f in [-0.5, 0.5]
  float p = 1.5403e-4f;
  p = fmaf(p, f, 1.3333558e-3f);
  p = fmaf(p, f, 9.6181291e-3f);
  p = fmaf(p, f, 5.5504109e-2f);
  p = fmaf(p, f, 2.4022651e-1f);
  p = fmaf(p, f, 6.9314718e-1f);
  p = fmaf(p, f, 1.0f);
  return __int_as_float(__float_as_int(p) + (e << 23));
}

__device__ __forceinline__ uint32_t pack_bf16(float x, float y) {
  __nv_bfloat162 t = __floats2bfloat162_rn(x, y);
  return *(uint32_t*)&t;
}

// ---------------------------------------------------------------------------
// fp32 -> bf16 hi/lo split
// ---------------------------------------------------------------------------
__global__ void cvt_split(const float* __restrict__ in,
                          __nv_bfloat16* __restrict__ hi,
                          __nv_bfloat16* __restrict__ lo, int n) {
  int i = (blockIdx.x * blockDim.x + threadIdx.x) * 4;
  if (i >= n) return;
  float4 v = *(const float4*)(in + i);
  __nv_bfloat16 h0 = __float2bfloat16_rn(v.x);
  __nv_bfloat16 h1 = __float2bfloat16_rn(v.y);
  __nv_bfloat16 h2 = __float2bfloat16_rn(v.z);
  __nv_bfloat16 h3 = __float2bfloat16_rn(v.w);
  __nv_bfloat16 l0 = __float2bfloat16_rn(v.x - __bfloat162float(h0));
  __nv_bfloat16 l1 = __float2bfloat16_rn(v.y - __bfloat162float(h1));
  __nv_bfloat16 l2 = __float2bfloat16_rn(v.z - __bfloat162float(h2));
  __nv_bfloat16 l3 = __float2bfloat16_rn(v.w - __bfloat162float(h3));
  union { __nv_bfloat16 b[4]; uint2 u; } H, L;
  H.b[0] = h0; H.b[1] = h1; H.b[2] = h2; H.b[3] = h3;
  L.b[0] = l0; L.b[1] = l1; L.b[2] = l2; L.b[3] = l3;
  *(uint2*)(hi + i) = H.u;
  *(uint2*)(lo + i) = L.u;
}

// ---------------------------------------------------------------------------
// HMMA bf16x3 GEMM (unchanged from round 3, passing)
// ---------------------------------------------------------------------------
#define BK 32
#define NCHUNK (HID / BK)
#define TSTR 40
#define TELEM (128 * TSTR)
#define BUFELEM (4 * TELEM)
#define GEMM_SMEM (2 * BUFELEM * 2)

__global__ __launch_bounds__(256, 1) void gemm_mma_bf16x3(
    const __nv_bfloat16* __restrict__ Ahi, const __nv_bfloat16* __restrict__ Alo,
    const __nv_bfloat16* __restrict__ Bhi, const __nv_bfloat16* __restrict__ Blo,
    const float* __restrict__ bias, float* __restrict__ C) {
  extern __shared__ __nv_bfloat16 smb[];
  const uint32_t sbase = smem_u32(smb);
  const int tid  = threadIdx.x;
  const int wid  = tid >> 5;
  const int lane = tid & 31;
  const int bm = blockIdx.y << 7;
  const int bn = blockIdx.x << 7;
  const int warp_m = (wid & 1) << 6;
  const int warp_n = (wid >> 1) << 5;

  const __nv_bfloat16* gp[4] = {
      Ahi + (size_t)bm * HID, Alo + (size_t)bm * HID,
      Bhi + (size_t)bn * HID, Blo + (size_t)bn * HID};

  auto issue_chunk = [&](int c) {
    const int p = c & 1;
    const int k0 = c * BK;
    const uint32_t s0 = sbase + p * BUFELEM * 2;
#pragma unroll
    for (int t = 0; t < 4; t++) {
#pragma unroll
      for (int i = 0; i < 2; i++) {
        int u = tid + (i << 8);
        int row = u >> 2;
        int cc = (u & 3) << 3;
        const __nv_bfloat16* ga = gp[t] + (size_t)row * HID + k0 + cc;
        uint32_t sa = s0 + (t * TELEM + row * TSTR + cc) * 2;
        CP_ASYNC16(sa, ga);
      }
    }
    CP_COMMIT();
  };

  float acc[4][4][4];
#pragma unroll
  for (int mt = 0; mt < 4; mt++)
#pragma unroll
    for (int nt = 0; nt < 4; nt++)
#pragma unroll
      for (int r = 0; r < 4; r++) acc[mt][nt][r] = 0.f;

  issue_chunk(0);

  for (int c = 0; c < NCHUNK; c++) {
    if (c + 1 < NCHUNK) { issue_chunk(c + 1); CP_WAIT1(); }
    else                { CP_WAIT0(); }
    __syncthreads();

    const uint32_t buf = sbase + (c & 1) * BUFELEM * 2;
    const uint32_t aHi = buf;
    const uint32_t aLo = buf + TELEM * 2;
    const uint32_t bHi = buf + 2 * TELEM * 2;
    const uint32_t bLo = buf + 3 * TELEM * 2;

#pragma unroll
    for (int ks = 0; ks < 2; ks++) {
      const int kc = ks << 4;
      uint32_t ah[4][4], al[4][4];
      const int arow = warp_m + (lane & 15);
      const int acol = kc + ((lane >> 4) << 3);
#pragma unroll
      for (int mt = 0; mt < 4; mt++) {
        uint32_t off = ((arow + (mt << 4)) * TSTR + acol) * 2;
        ldsm4(aHi + off, ah[mt][0], ah[mt][1], ah[mt][2], ah[mt][3]);
        ldsm4(aLo + off, al[mt][0], al[mt][1], al[mt][2], al[mt][3]);
      }
      uint32_t bh[4][2], bl[4][2];
      const int brow0 = (lane & 7) + ((lane >> 4) << 3);
      const int bcol  = kc + (((lane >> 3) & 1) << 3);
#pragma unroll
      for (int pr = 0; pr < 2; pr++) {
        const int nb = warp_n + (pr << 4);
        uint32_t off = ((nb + brow0) * TSTR + bcol) * 2;
        ldsm4(bHi + off, bh[pr*2][0], bh[pr*2][1], bh[pr*2+1][0], bh[pr*2+1][1]);
        ldsm4(bLo + off, bl[pr*2][0], bl[pr*2][1], bl[pr*2+1][0], bl[pr*2+1][1]);
      }
#pragma unroll
      for (int mt = 0; mt < 4; mt++)
#pragma unroll
        for (int nt = 0; nt < 4; nt++) {
          mma16816(acc[mt][nt], ah[mt], bh[nt]);
          mma16816(acc[mt][nt], ah[mt], bl[nt]);
          mma16816(acc[mt][nt], al[mt], bh[nt]);
        }
    }
    __syncthreads();
  }

  const int r  = lane >> 2;
  const int c2 = (lane & 3) << 1;
#pragma unroll
  for (int mt = 0; mt < 4; mt++) {
    const int row0 = bm + warp_m + (mt << 4) + r;
#pragma unroll
    for (int nt = 0; nt < 4; nt++) {
      const int col = bn + warp_n + (nt << 3) + c2;
      float b0 = 0.f, b1 = 0.f;
      if (bias) { b0 = bias[col]; b1 = bias[col + 1]; }
      float2 v0 = {acc[mt][nt][0] + b0, acc[mt][nt][1] + b1};
      float2 v1 = {acc[mt][nt][2] + b0, acc[mt][nt][3] + b1};
      *(float2*)&C[(size_t)row0 * HID + col]       = v0;
      *(float2*)&C[(size_t)(row0 + 8) * HID + col] = v1;
    }
  }
}

// ---------------------------------------------------------------------------
// RoPE + bf16 hi/lo split.  q gets scale*log2(e) folded in (exp2-domain
// softmax); k unscaled.
// ---------------------------------------------------------------------------
__global__ void rope_split(const float* __restrict__ q, const float* __restrict__ k,
                           const float* __restrict__ cosb, const float* __restrict__ sinb,
                           __nv_bfloat16* __restrict__ qhi, __nv_bfloat16* __restrict__ qlo,
                           __nv_bfloat16* __restrict__ khi, __nv_bfloat16* __restrict__ klo)
{
  const float SC = 0.08838834764831845f * 1.4426950408889634f;
  int i = blockIdx.x * blockDim.x + threadIdx.x;
  int d  = i & 63;
  int h  = (i >> 6) & 15;
  int ms = i >> 10;
  int s  = ms & (S_LEN - 1);
  size_t base = (size_t)ms * HID + (size_t)h * HD;

  float c1 = cosb[s * HD + d],      s1 = sinb[s * HD + d];
  float c2 = cosb[s * HD + d + 64], s2 = sinb[s * HD + d + 64];

  float q1 = q[base + d], q2 = q[base + d + 64];
  float qa = (q1 * c1 - q2 * s1) * SC;
  float qb = (q2 * c2 + q1 * s2) * SC;
  float k1 = k[base + d], k2 = k[base + d + 64];
  float ka = k1 * c1 - k2 * s1;
  float kb = k2 * c2 + k1 * s2;

  __nv_bfloat16 t;
  t = __float2bfloat16_rn(qa); qhi[base + d]      = t; qlo[base + d]      = __float2bfloat16_rn(qa - __bfloat162float(t));
  t = __float2bfloat16_rn(qb); qhi[base + d + 64] = t; qlo[base + d + 64] = __float2bfloat16_rn(qb - __bfloat162float(t));
  t = __float2bfloat16_rn(ka); khi[base + d]      = t; klo[base + d]      = __float2bfloat16_rn(ka - __bfloat162float(t));
  t = __float2bfloat16_rn(kb); khi[base + d + 64] = t; klo[base + d + 64] = __float2bfloat16_rn(kb - __bfloat162float(t));
}

// ---------------------------------------------------------------------------
// HMMA flash attention, bf16x3 for QK^T and PV, exp2-domain softmax.
// CTA: 128 q-rows x one (b,h). 8 warps x 16 q-rows. kv chunks of 64, 2-stage.
// smem: Qhi/Qlo [128][136]; 2 x {Khi,Klo,Vhi,Vlo}[64][136].
// ---------------------------------------------------------------------------
#define ASTR 136
#define QT_ELEM (128 * ASTR)             // per Q array
#define KV_ELEM (64 * ASTR)              // per kv array
#define KVBUF_ELEM (4 * KV_ELEM)
#define A_SMEM ((2 * QT_ELEM + 2 * KVBUF_ELEM) * 2)   // 208896 bytes

__global__ __launch_bounds__(256, 1) void attn_mma(
    const __nv_bfloat16* __restrict__ qhi, const __nv_bfloat16* __restrict__ qlo,
    const __nv_bfloat16* __restrict__ khi, const __nv_bfloat16* __restrict__ klo,
    const __nv_bfloat16* __restrict__ vhi, const __nv_bfloat16* __restrict__ vlo,
    float* __restrict__ O)
{
  extern __shared__ __nv_bfloat16 sma[];
  const uint32_t sb = smem_u32(sma);
  const int tid  = threadIdx.x;
  const int wid  = tid >> 5;
  const int lane = tid & 31;
  const int q0 = blockIdx.x << 7;
  const int b  = blockIdx.y >> 4;
  const int h  = blockIdx.y & 15;
  const int warp_m = wid << 4;

  const size_t bS = (size_t)b * S_LEN;
  const size_t h128 = (size_t)h * HD;

  const uint32_t sQhi = sb;
  const uint32_t sQlo = sb + QT_ELEM * 2;
  const uint32_t sKV0 = sb + 2 * QT_ELEM * 2;

  // ---- issue Q + kv0 (group 0), kv1 (group 1)
#pragma unroll
  for (int i = 0; i < 8; i++) {
    int u = tid + (i << 8);
    int row = u >> 4, c8 = (u & 15) << 3;
    size_t g = (bS + q0 + row) * HID + h128 + c8;
    uint32_t so = (uint32_t)(row * ASTR + c8) * 2;
    CP_ASYNC16(sQhi + so, qhi + g);
    CP_ASYNC16(sQlo + so, qlo + g);
  }
  auto issue_kv = [&](int t) {
    const uint32_t bufb = sKV0 + (t & 1) * KVBUF_ELEM * 2;
    const int kv0 = t << 6;
#pragma unroll
    for (int i = 0; i < 4; i++) {
      int u = tid + (i << 8);
      int row = u >> 4, c8 = (u & 15) << 3;
      size_t g = (bS + kv0 + row) * HID + h128 + c8;
      uint32_t so = (uint32_t)(row * ASTR + c8) * 2;
      CP_ASYNC16(bufb + so,                   khi + g);
      CP_ASYNC16(bufb + KV_ELEM * 2 + so,     klo + g);
      CP_ASYNC16(bufb + 2 * KV_ELEM * 2 + so, vhi + g);
      CP_ASYNC16(bufb + 3 * KV_ELEM * 2 + so, vlo + g);
    }
    CP_COMMIT();
  };
  issue_kv(0);
  issue_kv(1);

  float m0 = -1e30f, m1 = -1e30f, l0 = 0.f, l1 = 0.f;
  float Oa[16][4];
#pragma unroll
  for (int j = 0; j < 16; j++)
#pragma unroll
    for (int r = 0; r < 4; r++) Oa[j][r] = 0.f;

  const int NT = S_LEN / 64;   // 32
  for (int t = 0; t < NT; t++) {
    if (t < NT - 1) CP_WAIT1(); else CP_WAIT0();
    __syncthreads();

    const uint32_t buf  = sKV0 + (t & 1) * KVBUF_ELEM * 2;
    const uint32_t sKhi = buf;
    const uint32_t sKlo = buf + KV_ELEM * 2;
    const uint32_t sVhi = buf + 2 * KV_ELEM * 2;
    const uint32_t sVlo = buf + 3 * KV_ELEM * 2;

    // ---- S = Q K^T  (exp2-domain, scale folded into q)
    float S[8][4];
#pragma unroll
    for (int j = 0; j < 8; j++)
#pragma unroll
      for (int r = 0; r < 4; r++) S[j][r] = 0.f;

#pragma unroll
    for (int kc = 0; kc < 8; kc++) {
      uint32_t aH[4], aL[4];
      const uint32_t qoff =
          (uint32_t)((warp_m + (lane & 15)) * ASTR + (kc << 4) + ((lane >> 4) << 3)) * 2;
      ldsm4(sQhi + qoff, aH[0], aH[1], aH[2], aH[3]);
      ldsm4(sQlo + qoff, aL[0], aL[1], aL[2], aL[3]);
#pragma unroll
      for (int np = 0; np < 4; np++) {
        uint32_t bH[4], bL[4];
        const uint32_t koff =
            (uint32_t)(((np << 4) + (lane & 7) + (((lane >> 4) & 1) << 3)) * ASTR
                       + (kc << 4) + (((lane >> 3) & 1) << 3)) * 2;
        ldsm4(sKhi + koff, bH[0], bH[1], bH[2], bH[3]);
        ldsm4(sKlo + koff, bL[0], bL[1], bL[2], bL[3]);
        mma16816(S[np * 2],     aH, bH);
        mma16816(S[np * 2],     aH, bL);
        mma16816(S[np * 2],     aL, bH);
        mma16816(S[np * 2 + 1], aH, bH + 2);
        mma16816(S[np * 2 + 1], aH, bL + 2);
        mma16816(S[np * 2 + 1], aL, bH + 2);
      }
    }

    // ---- online softmax (exp2 domain), rows r=lane>>2 and r+8
    float mx0 = m0, mx1 = m1;
#pragma unroll
    for (int j = 0; j < 8; j++) {
      mx0 = fmaxf(mx0, fmaxf(S[j][0], S[j][1]));
      mx1 = fmaxf(mx1, fmaxf(S[j][2], S[j][3]));
    }
    mx0 = fmaxf(mx0, __shfl_xor_sync(0xffffffffu, mx0, 1));
    mx0 = fmaxf(mx0, __shfl_xor_sync(0xffffffffu, mx0, 2));
    mx1 = fmaxf(mx1, __shfl_xor_sync(0xffffffffu, mx1, 1));
    mx1 = fmaxf(mx1, __shfl_xor_sync(0xffffffffu, mx1, 2));
    const float al0 = exp2p(m0 - mx0);
    const float al1 = exp2p(m1 - mx1);
    m0 = mx0; m1 = mx1;

    uint32_t ph[8][2], pl[8][2];
    float sum0 = 0.f, sum1 = 0.f;
#pragma unroll
    for (int j = 0; j < 8; j++) {
      float p00 = exp2p(S[j][0] - mx0);
      float p01 = exp2p(S[j][1] - mx0);
      float p10 = exp2p(S[j][2] - mx1);
      float p11 = exp2p(S[j][3] - mx1);
      sum0 += p00 + p01;
      sum1 += p10 + p11;
      float h00 = __bfloat162float(__float2bfloat16_rn(p00));
      float h01 = __bfloat162float(__float2bfloat16_rn(p01));
      float h10 = __bfloat162float(__float2bfloat16_rn(p10));
      float h11 = __bfloat162float(__float2bfloat16_rn(p11));
      ph[j][0] = pack_bf16(h00, h01);
      ph[j][1] = pack_bf16(h10, h11);
      pl[j][0] = pack_bf16(p00 - h00, p01 - h01);
      pl[j][1] = pack_bf16(p10 - h10, p11 - h11);
    }
    l0 = l0 * al0 + sum0;
    l1 = l1 * al1 + sum1;
#pragma unroll
    for (int j = 0; j < 16; j++) {
      Oa[j][0] *= al0; Oa[j][1] *= al0;
      Oa[j][2] *= al1; Oa[j][3] *= al1;
    }

    // ---- O += P V   (P A-frags straight from registers)
#pragma unroll
    for (int kk = 0; kk < 4; kk++) {
      uint32_t paH[4] = {ph[kk*2][0], ph[kk*2][1], ph[kk*2+1][0], ph[kk*2+1][1]};
      uint32_t paL[4] = {pl[kk*2][0], pl[kk*2][1], pl[kk*2+1][0], pl[kk*2+1][1]};
#pragma unroll
      for (int dp = 0; dp < 8; dp++) {
        uint32_t bH[4], bL[4];
        const uint32_t voff =
            (uint32_t)(((kk << 4) + (lane & 7) + (((lane >> 3) & 1) << 3)) * ASTR
                       + (dp << 4) + ((lane >> 4) << 3)) * 2;
        ldsm4t(sVhi + voff, bH[0], bH[1], bH[2], bH[3]);
        ldsm4t(sVlo + voff, bL[0], bL[1], bL[2], bL[3]);
        mma16816(Oa[dp * 2],     paH, bH);
        mma16816(Oa[dp * 2],     paH, bL);
        mma16816(Oa[dp * 2],     paL, bH);
        mma16816(Oa[dp * 2 + 1], paH, bH + 2);
        mma16816(Oa[dp * 2 + 1], paH, bL + 2);
        mma16816(Oa[dp * 2 + 1], paL, bH + 2);
      }
    }

    __syncthreads();
    if (t + 2 < NT) issue_kv(t + 2);
  }

  // ---- epilogue
  l0 += __shfl_xor_sync(0xffffffffu, l0, 1);
  l0 += __shfl_xor_sync(0xffffffffu, l0, 2);
  l1 += __shfl_xor_sync(0xffffffffu, l1, 1);
  l1 += __shfl_xor_sync(0xffffffffu, l1, 2);
  const float inv0 = 1.f / l0;
  const float inv1 = 1.f / l1;
  const int row0 = q0 + warp_m + (lane >> 2);
  const int cofs = (lane & 3) << 1;
#pragma unroll
  for (int j = 0; j < 16; j++) {
    const int col = (j << 3) + cofs;
    float2 v0 = {Oa[j][0] * inv0, Oa[j][1] * inv0};
    float2 v1 = {Oa[j][2] * inv1, Oa[j][3] * inv1};
    *(float2*)&O[(bS + row0) * HID + h128 + col]     = v0;
    *(float2*)&O[(bS + row0 + 8) * HID + h128 + col] = v1;
  }
}

// ---------------------------------------------------------------------------
extern "C" void kernel_launch(void* const* d_in, const int* in_sizes, int n_in,
                              void* d_out, int out_size)
{
  (void)in_sizes; (void)n_in; (void)out_size;
  const float* x    = (const float*)d_in[0];
  const float* cosb = (const float*)d_in[1];
  const float* sinb = (const float*)d_in[2];
  const float* wq   = (const float*)d_in[3];
  const float* bq   = (const float*)d_in[4];
  const float* wk   = (const float*)d_in[5];
  const float* bk   = (const float*)d_in[6];
  const float* wv   = (const float*)d_in[7];
  const float* bv   = (const float*)d_in[8];
  const float* wo   = (const float*)d_in[9];
  float* out = (float*)d_out;

  float *q, *k, *v, *ao;
  cudaGetSymbolAddress((void**)&q,  g_q);
  cudaGetSymbolAddress((void**)&k,  g_k);
  cudaGetSymbolAddress((void**)&v,  g_v);
  cudaGetSymbolAddress((void**)&ao, g_ao);

  __nv_bfloat16 *xhi, *xlo, *whi, *wlo, *aohi, *aolo;
  __nv_bfloat16 *qhi, *qlo, *khi, *klo, *vhi, *vlo;
  cudaGetSymbolAddress((void**)&xhi,  g_xhi);
  cudaGetSymbolAddress((void**)&xlo,  g_xlo);
  cudaGetSymbolAddress((void**)&whi,  g_whi);
  cudaGetSymbolAddress((void**)&wlo,  g_wlo);
  cudaGetSymbolAddress((void**)&aohi, g_aohi);
  cudaGetSymbolAddress((void**)&aolo, g_aolo);
  cudaGetSymbolAddress((void**)&qhi,  g_qhi);
  cudaGetSymbolAddress((void**)&qlo,  g_qlo);
  cudaGetSymbolAddress((void**)&khi,  g_khi);
  cudaGetSymbolAddress((void**)&klo,  g_klo);
  cudaGetSymbolAddress((void**)&vhi,  g_vhi);
  cudaGetSymbolAddress((void**)&vlo,  g_vlo);

  static bool attrs_set = false;
  if (!attrs_set) {
    cudaFuncSetAttribute(gemm_mma_bf16x3,
                         cudaFuncAttributeMaxDynamicSharedMemorySize, GEMM_SMEM);
    cudaFuncSetAttribute(attn_mma,
                         cudaFuncAttributeMaxDynamicSharedMemorySize, A_SMEM);
    attrs_set = true;
  }

  const int NX = MROWS * HID;
  const int NW = HID * HID;
  const size_t WSTRIDE = (size_t)HID * HID;

  cvt_split<<<NX / 1024, 256>>>(x,  xhi, xlo, NX);
  cvt_split<<<NW / 1024, 256>>>(wq, whi + 0 * WSTRIDE, wlo + 0 * WSTRIDE, NW);
  cvt_split<<<NW / 1024, 256>>>(wk, whi + 1 * WSTRIDE, wlo + 1 * WSTRIDE, NW);
  cvt_split<<<NW / 1024, 256>>>(wv, whi + 2 * WSTRIDE, wlo + 2 * WSTRIDE, NW);
  cvt_split<<<NW / 1024, 256>>>(wo, whi + 3 * WSTRIDE, wlo + 3 * WSTRIDE, NW);

  dim3 gg(HID / 128, MROWS / 128);  // (16, 32)
  gemm_mma_bf16x3<<<gg, 256, GEMM_SMEM>>>(xhi, xlo, whi + 0 * WSTRIDE, wlo + 0 * WSTRIDE, bq, q);
  gemm_mma_bf16x3<<<gg, 256, GEMM_SMEM>>>(xhi, xlo, whi + 1 * WSTRIDE, wlo + 1 * WSTRIDE, bk, k);
  gemm_mma_bf16x3<<<gg, 256, GEMM_SMEM>>>(xhi, xlo, whi + 2 * WSTRIDE, wlo + 2 * WSTRIDE, bv, v);

  rope_split<<<(MROWS * NH * 64) / 256, 256>>>(q, k, cosb, sinb, qhi, qlo, khi, klo);
  cvt_split<<<NX / 1024, 256>>>(v, vhi, vlo, NX);

  attn_mma<<<dim3(S_LEN / 128, BATCH * NH), 256, A_SMEM>>>(qhi, qlo, khi, klo, vhi, vlo, ao);

  cvt_split<<<NX / 1024, 256>>>(ao, aohi, aolo, NX);
  gemm_mma_bf16x3<<<gg, 256, GEMM_SMEM>>>(aohi, aolo, whi + 3 * WSTRIDE, wlo + 3 * WSTRIDE, nullptr, out);
}

// round 5
// speedup vs baseline: 2.9454x; 1.2855x over previous
#include <cuda_runtime.h>
#include <cuda_bf16.h>
#include <cstdint>
#include <cstddef>

#define S_LEN 2048
#define HID   2048
#define NH    16
#define HD    128
#define BATCH 2
#define MROWS (BATCH * S_LEN)

// ---------------------------------------------------------------------------
// Scratch (allocation-free rule: device globals)
// ---------------------------------------------------------------------------
__device__ float g_q [(size_t)MROWS * HID];
__device__ float g_k [(size_t)MROWS * HID];
__device__ float g_v [(size_t)MROWS * HID];
__device__ float g_ao[(size_t)MROWS * HID];

__device__ __nv_bfloat16 g_qhi[(size_t)MROWS * HID];
__device__ __nv_bfloat16 g_qlo[(size_t)MROWS * HID];
__device__ __nv_bfloat16 g_khi[(size_t)MROWS * HID];
__device__ __nv_bfloat16 g_klo[(size_t)MROWS * HID];
__device__ __nv_bfloat16 g_vhi[(size_t)MROWS * HID];
__device__ __nv_bfloat16 g_vlo[(size_t)MROWS * HID];

// ---------------------------------------------------------------------------
// helpers
// ---------------------------------------------------------------------------
__device__ __forceinline__ uint32_t smem_u32(const void* p) {
  uint32_t a;
  asm("{ .reg .u64 t; cvta.to.shared.u64 t, %1; cvt.u32.u64 %0, t; }"
      : "=r"(a) : "l"(p));
  return a;
}

__device__ __forceinline__ void ldsm4(uint32_t addr, uint32_t& r0, uint32_t& r1,
                                      uint32_t& r2, uint32_t& r3) {
  asm volatile("ldmatrix.sync.aligned.m8n8.x4.shared.b16 {%0,%1,%2,%3}, [%4];"
               : "=r"(r0), "=r"(r1), "=r"(r2), "=r"(r3) : "r"(addr));
}

__device__ __forceinline__ void ldsm4t(uint32_t addr, uint32_t& r0, uint32_t& r1,
                                       uint32_t& r2, uint32_t& r3) {
  asm volatile("ldmatrix.sync.aligned.m8n8.x4.trans.shared.b16 {%0,%1,%2,%3}, [%4];"
               : "=r"(r0), "=r"(r1), "=r"(r2), "=r"(r3) : "r"(addr));
}

__device__ __forceinline__ void mma16816(float* d, const uint32_t* a,
                                         const uint32_t* b) {
  asm volatile(
      "mma.sync.aligned.m16n8k16.row.col.f32.bf16.bf16.f32 "
      "{%0,%1,%2,%3}, {%4,%5,%6,%7}, {%8,%9}, {%0,%1,%2,%3};"
      : "+f"(d[0]), "+f"(d[1]), "+f"(d[2]), "+f"(d[3])
      : "r"(a[0]), "r"(a[1]), "r"(a[2]), "r"(a[3]), "r"(b[0]), "r"(b[1]));
}

__device__ __forceinline__ void mma1688_tf32(float* d, const uint32_t* a,
                                             const uint32_t* b) {
  asm volatile(
      "mma.sync.aligned.m16n8k8.row.col.f32.tf32.tf32.f32 "
      "{%0,%1,%2,%3}, {%4,%5,%6,%7}, {%8,%9}, {%0,%1,%2,%3};"
      : "+f"(d[0]), "+f"(d[1]), "+f"(d[2]), "+f"(d[3])
      : "r"(a[0]), "r"(a[1]), "r"(a[2]), "r"(a[3]), "r"(b[0]), "r"(b[1]));
}

__device__ __forceinline__ uint32_t f2tf32(float x) {
  uint32_t r;
  asm("cvt.rna.tf32.f32 %0, %1;" : "=r"(r) : "f"(x));
  return r;
}

#define CP_ASYNC16(saddr, gaddr) \
  asm volatile("cp.async.cg.shared.global [%0], [%1], 16;" \
               :: "r"(saddr), "l"(gaddr))
#define CP_COMMIT() asm volatile("cp.async.commit_group;")
#define CP_WAIT1()  asm volatile("cp.async.wait_group 1;")
#define CP_WAIT0()  asm volatile("cp.async.wait_group 0;")

// FFMA-only exp2 (no MUFU): magic-round + degree-6 Taylor, |err| < 2e-7.
__device__ __forceinline__ float exp2p(float x) {
  x = fmaxf(x, -126.f);
  float r = x + 12582912.f;
  int   e = __float_as_int(r) - 0x4B400000;
  float f = x - (r - 12582912.f);
  float p = 1.5403e-4f;
  p = fmaf(p, f, 1.3333558e-3f);
  p = fmaf(p, f, 9.6181291e-3f);
  p = fmaf(p, f, 5.5504109e-2f);
  p = fmaf(p, f, 2.4022651e-1f);
  p = fmaf(p, f, 6.9314718e-1f);
  p = fmaf(p, f, 1.0f);
  return __int_as_float(__float_as_int(p) + (e << 23));
}

__device__ __forceinline__ uint32_t pack_bf16(float x, float y) {
  __nv_bfloat162 t = __floats2bfloat162_rn(x, y);
  return *(uint32_t*)&t;
}

// ---------------------------------------------------------------------------
// fp32 -> bf16 hi/lo split (still used for V)
// ---------------------------------------------------------------------------
__global__ void cvt_split(const float* __restrict__ in,
                          __nv_bfloat16* __restrict__ hi,
                          __nv_bfloat16* __restrict__ lo, int n) {
  int i = (blockIdx.x * blockDim.x + threadIdx.x) * 4;
  if (i >= n) return;
  float4 v = *(const float4*)(in + i);
  __nv_bfloat16 h0 = __float2bfloat16_rn(v.x);
  __nv_bfloat16 h1 = __float2bfloat16_rn(v.y);
  __nv_bfloat16 h2 = __float2bfloat16_rn(v.z);
  __nv_bfloat16 h3 = __float2bfloat16_rn(v.w);
  __nv_bfloat16 l0 = __float2bfloat16_rn(v.x - __bfloat162float(h0));
  __nv_bfloat16 l1 = __float2bfloat16_rn(v.y - __bfloat162float(h1));
  __nv_bfloat16 l2 = __float2bfloat16_rn(v.z - __bfloat162float(h2));
  __nv_bfloat16 l3 = __float2bfloat16_rn(v.w - __bfloat162float(h3));
  union { __nv_bfloat16 b[4]; uint2 u; } H, L;
  H.b[0] = h0; H.b[1] = h1; H.b[2] = h2; H.b[3] = h3;
  L.b[0] = l0; L.b[1] = l1; L.b[2] = l2; L.b[3] = l3;
  *(uint2*)(hi + i) = H.u;
  *(uint2*)(lo + i) = L.u;
}

// ---------------------------------------------------------------------------
// TF32 single-pass GEMM: C[m,n] = sum_k A[m,k]*W[n,k] (+ bias[n])
// Raw fp32 inputs; cvt.rna.tf32 in-register. CTA 128x128, BK=32,
// 8 warps of 64x32, double-buffered cp.async, 2 CTAs/SM.
// smem rows: 32 floats + 4 pad (stride 36) -> conflict-free LDS frags.
// ---------------------------------------------------------------------------
#define BKT 32
#define NCHT (HID / BKT)          // 64
#define TSTRT 36                  // floats per smem row
#define TELEMT (128 * TSTRT)      // floats per tile
#define GEMM_T_SMEM (2 * 2 * TELEMT * 4)   // 73728 bytes

__global__ __launch_bounds__(256, 2) void gemm_tf32(
    const float* __restrict__ A, const float* __restrict__ W,
    const float* __restrict__ bias, float* __restrict__ C) {
  extern __shared__ float smf[];
  const uint32_t sbase = smem_u32(smf);
  const int tid  = threadIdx.x;
  const int wid  = tid >> 5;
  const int lane = tid & 31;
  const int bm = blockIdx.y << 7;
  const int bn = blockIdx.x << 7;
  const int warp_m = (wid & 1) << 6;   // 0 or 64
  const int warp_n = (wid >> 1) << 5;  // 0,32,64,96

  const float* gp[2] = {A + (size_t)bm * HID, W + (size_t)bn * HID};

  auto issue_chunk = [&](int c) {
    const int p = c & 1;
    const int k0 = c * BKT;
    const uint32_t s0 = sbase + p * 2 * TELEMT * 4;
#pragma unroll
    for (int t = 0; t < 2; t++) {
#pragma unroll
      for (int i = 0; i < 4; i++) {
        int u = tid + (i << 8);
        int row = u >> 3;
        int g = (u & 7) << 2;
        const float* ga = gp[t] + (size_t)row * HID + k0 + g;
        uint32_t sa = s0 + (t * TELEMT + row * TSTRT + g) * 4;
        CP_ASYNC16(sa, ga);
      }
    }
    CP_COMMIT();
  };

  float acc[4][4][4];
#pragma unroll
  for (int mt = 0; mt < 4; mt++)
#pragma unroll
    for (int nt = 0; nt < 4; nt++)
#pragma unroll
      for (int r = 0; r < 4; r++) acc[mt][nt][r] = 0.f;

  issue_chunk(0);

  for (int c = 0; c < NCHT; c++) {
    if (c + 1 < NCHT) { issue_chunk(c + 1); CP_WAIT1(); }
    else              { CP_WAIT0(); }
    __syncthreads();

    const float* sA = smf + (c & 1) * 2 * TELEMT;
    const float* sB = sA + TELEMT;

#pragma unroll
    for (int ks = 0; ks < 4; ks++) {
      const int kc = ks << 3;
      uint32_t a[4][4];
      const int r0 = warp_m + (lane >> 2);
      const int ca = kc + (lane & 3);
#pragma unroll
      for (int mt = 0; mt < 4; mt++) {
        const int rr = r0 + (mt << 4);
        a[mt][0] = f2tf32(sA[rr * TSTRT + ca]);
        a[mt][1] = f2tf32(sA[(rr + 8) * TSTRT + ca]);
        a[mt][2] = f2tf32(sA[rr * TSTRT + ca + 4]);
        a[mt][3] = f2tf32(sA[(rr + 8) * TSTRT + ca + 4]);
      }
      uint32_t b[4][2];
      const int n0 = warp_n + (lane >> 2);
      const int cb = kc + (lane & 3);
#pragma unroll
      for (int nt = 0; nt < 4; nt++) {
        const int nn = n0 + (nt << 3);
        b[nt][0] = f2tf32(sB[nn * TSTRT + cb]);
        b[nt][1] = f2tf32(sB[nn * TSTRT + cb + 4]);
      }
#pragma unroll
      for (int mt = 0; mt < 4; mt++)
#pragma unroll
        for (int nt = 0; nt < 4; nt++)
          mma1688_tf32(acc[mt][nt], a[mt], b[nt]);
    }
    __syncthreads();
  }

  const int r  = lane >> 2;
  const int c2 = (lane & 3) << 1;
#pragma unroll
  for (int mt = 0; mt < 4; mt++) {
    const int row0 = bm + warp_m + (mt << 4) + r;
#pragma unroll
    for (int nt = 0; nt < 4; nt++) {
      const int col = bn + warp_n + (nt << 3) + c2;
      float b0 = 0.f, b1 = 0.f;
      if (bias) { b0 = bias[col]; b1 = bias[col + 1]; }
      float2 v0 = {acc[mt][nt][0] + b0, acc[mt][nt][1] + b1};
      float2 v1 = {acc[mt][nt][2] + b0, acc[mt][nt][3] + b1};
      *(float2*)&C[(size_t)row0 * HID + col]       = v0;
      *(float2*)&C[(size_t)(row0 + 8) * HID + col] = v1;
    }
  }
}

// ---------------------------------------------------------------------------
// RoPE + bf16 hi/lo split. q gets scale*log2(e) folded in.
// ---------------------------------------------------------------------------
__global__ void rope_split(const float* __restrict__ q, const float* __restrict__ k,
                           const float* __restrict__ cosb, const float* __restrict__ sinb,
                           __nv_bfloat16* __restrict__ qhi, __nv_bfloat16* __restrict__ qlo,
                           __nv_bfloat16* __restrict__ khi, __nv_bfloat16* __restrict__ klo)
{
  const float SC = 0.08838834764831845f * 1.4426950408889634f;
  int i = blockIdx.x * blockDim.x + threadIdx.x;
  int d  = i & 63;
  int h  = (i >> 6) & 15;
  int ms = i >> 10;
  int s  = ms & (S_LEN - 1);
  size_t base = (size_t)ms * HID + (size_t)h * HD;

  float c1 = cosb[s * HD + d],      s1 = sinb[s * HD + d];
  float c2 = cosb[s * HD + d + 64], s2 = sinb[s * HD + d + 64];

  float q1 = q[base + d], q2 = q[base + d + 64];
  float qa = (q1 * c1 - q2 * s1) * SC;
  float qb = (q2 * c2 + q1 * s2) * SC;
  float k1 = k[base + d], k2 = k[base + d + 64];
  float ka = k1 * c1 - k2 * s1;
  float kb = k2 * c2 + k1 * s2;

  __nv_bfloat16 t;
  t = __float2bfloat16_rn(qa); qhi[base + d]      = t; qlo[base + d]      = __float2bfloat16_rn(qa - __bfloat162float(t));
  t = __float2bfloat16_rn(qb); qhi[base + d + 64] = t; qlo[base + d + 64] = __float2bfloat16_rn(qb - __bfloat162float(t));
  t = __float2bfloat16_rn(ka); khi[base + d]      = t; klo[base + d]      = __float2bfloat16_rn(ka - __bfloat162float(t));
  t = __float2bfloat16_rn(kb); khi[base + d + 64] = t; klo[base + d + 64] = __float2bfloat16_rn(kb - __bfloat162float(t));
}

// ---------------------------------------------------------------------------
// HMMA flash attention, bf16x3, exp2-domain softmax (unchanged, passing)
// ---------------------------------------------------------------------------
#define ASTR 136
#define QT_ELEM (128 * ASTR)
#define KV_ELEM (64 * ASTR)
#define KVBUF_ELEM (4 * KV_ELEM)
#define A_SMEM ((2 * QT_ELEM + 2 * KVBUF_ELEM) * 2)

__global__ __launch_bounds__(256, 1) void attn_mma(
    const __nv_bfloat16* __restrict__ qhi, const __nv_bfloat16* __restrict__ qlo,
    const __nv_bfloat16* __restrict__ khi, const __nv_bfloat16* __restrict__ klo,
    const __nv_bfloat16* __restrict__ vhi, const __nv_bfloat16* __restrict__ vlo,
    float* __restrict__ O)
{
  extern __shared__ __nv_bfloat16 sma[];
  const uint32_t sb = smem_u32(sma);
  const int tid  = threadIdx.x;
  const int wid  = tid >> 5;
  const int lane = tid & 31;
  const int q0 = blockIdx.x << 7;
  const int b  = blockIdx.y >> 4;
  const int h  = blockIdx.y & 15;
  const int warp_m = wid << 4;

  const size_t bS = (size_t)b * S_LEN;
  const size_t h128 = (size_t)h * HD;

  const uint32_t sQhi = sb;
  const uint32_t sQlo = sb + QT_ELEM * 2;
  const uint32_t sKV0 = sb + 2 * QT_ELEM * 2;

#pragma unroll
  for (int i = 0; i < 8; i++) {
    int u = tid + (i << 8);
    int row = u >> 4, c8 = (u & 15) << 3;
    size_t g = (bS + q0 + row) * HID + h128 + c8;
    uint32_t so = (uint32_t)(row * ASTR + c8) * 2;
    CP_ASYNC16(sQhi + so, qhi + g);
    CP_ASYNC16(sQlo + so, qlo + g);
  }
  auto issue_kv = [&](int t) {
    const uint32_t bufb = sKV0 + (t & 1) * KVBUF_ELEM * 2;
    const int kv0 = t << 6;
#pragma unroll
    for (int i = 0; i < 4; i++) {
      int u = tid + (i << 8);
      int row = u >> 4, c8 = (u & 15) << 3;
      size_t g = (bS + kv0 + row) * HID + h128 + c8;
      uint32_t so = (uint32_t)(row * ASTR + c8) * 2;
      CP_ASYNC16(bufb + so,                   khi + g);
      CP_ASYNC16(bufb + KV_ELEM * 2 + so,     klo + g);
      CP_ASYNC16(bufb + 2 * KV_ELEM * 2 + so, vhi + g);
      CP_ASYNC16(bufb + 3 * KV_ELEM * 2 + so, vlo + g);
    }
    CP_COMMIT();
  };
  issue_kv(0);
  issue_kv(1);

  float m0 = -1e30f, m1 = -1e30f, l0 = 0.f, l1 = 0.f;
  float Oa[16][4];
#pragma unroll
  for (int j = 0; j < 16; j++)
#pragma unroll
    for (int r = 0; r < 4; r++) Oa[j][r] = 0.f;

  const int NT = S_LEN / 64;
  for (int t = 0; t < NT; t++) {
    if (t < NT - 1) CP_WAIT1(); else CP_WAIT0();
    __syncthreads();

    const uint32_t buf  = sKV0 + (t & 1) * KVBUF_ELEM * 2;
    const uint32_t sKhi = buf;
    const uint32_t sKlo = buf + KV_ELEM * 2;
    const uint32_t sVhi = buf + 2 * KV_ELEM * 2;
    const uint32_t sVlo = buf + 3 * KV_ELEM * 2;

    float S[8][4];
#pragma unroll
    for (int j = 0; j < 8; j++)
#pragma unroll
      for (int r = 0; r < 4; r++) S[j][r] = 0.f;

#pragma unroll
    for (int kc = 0; kc < 8; kc++) {
      uint32_t aH[4], aL[4];
      const uint32_t qoff =
          (uint32_t)((warp_m + (lane & 15)) * ASTR + (kc << 4) + ((lane >> 4) << 3)) * 2;
      ldsm4(sQhi + qoff, aH[0], aH[1], aH[2], aH[3]);
      ldsm4(sQlo + qoff, aL[0], aL[1], aL[2], aL[3]);
#pragma unroll
      for (int np = 0; np < 4; np++) {
        uint32_t bH[4], bL[4];
        const uint32_t koff =
            (uint32_t)(((np << 4) + (lane & 7) + (((lane >> 4) & 1) << 3)) * ASTR
                       + (kc << 4) + (((lane >> 3) & 1) << 3)) * 2;
        ldsm4(sKhi + koff, bH[0], bH[1], bH[2], bH[3]);
        ldsm4(sKlo + koff, bL[0], bL[1], bL[2], bL[3]);
        mma16816(S[np * 2],     aH, bH);
        mma16816(S[np * 2],     aH, bL);
        mma16816(S[np * 2],     aL, bH);
        mma16816(S[np * 2 + 1], aH, bH + 2);
        mma16816(S[np * 2 + 1], aH, bL + 2);
        mma16816(S[np * 2 + 1], aL, bH + 2);
      }
    }

    float mx0 = m0, mx1 = m1;
#pragma unroll
    for (int j = 0; j < 8; j++) {
      mx0 = fmaxf(mx0, fmaxf(S[j][0], S[j][1]));
      mx1 = fmaxf(mx1, fmaxf(S[j][2], S[j][3]));
    }
    mx0 = fmaxf(mx0, __shfl_xor_sync(0xffffffffu, mx0, 1));
    mx0 = fmaxf(mx0, __shfl_xor_sync(0xffffffffu, mx0, 2));
    mx1 = fmaxf(mx1, __shfl_xor_sync(0xffffffffu, mx1, 1));
    mx1 = fmaxf(mx1, __shfl_xor_sync(0xffffffffu, mx1, 2));
    const float al0 = exp2p(m0 - mx0);
    const float al1 = exp2p(m1 - mx1);
    m0 = mx0; m1 = mx1;

    uint32_t ph[8][2], pl[8][2];
    float sum0 = 0.f, sum1 = 0.f;
#pragma unroll
    for (int j = 0; j < 8; j++) {
      float p00 = exp2p(S[j][0] - mx0);
      float p01 = exp2p(S[j][1] - mx0);
      float p10 = exp2p(S[j][2] - mx1);
      float p11 = exp2p(S[j][3] - mx1);
      sum0 += p00 + p01;
      sum1 += p10 + p11;
      float h00 = __bfloat162float(__float2bfloat16_rn(p00));
      float h01 = __bfloat162float(__float2bfloat16_rn(p01));
      float h10 = __bfloat162float(__float2bfloat16_rn(p10));
      float h11 = __bfloat162float(__float2bfloat16_rn(p11));
      ph[j][0] = pack_bf16(h00, h01);
      ph[j][1] = pack_bf16(h10, h11);
      pl[j][0] = pack_bf16(p00 - h00, p01 - h01);
      pl[j][1] = pack_bf16(p10 - h10, p11 - h11);
    }
    l0 = l0 * al0 + sum0;
    l1 = l1 * al1 + sum1;
#pragma unroll
    for (int j = 0; j < 16; j++) {
      Oa[j][0] *= al0; Oa[j][1] *= al0;
      Oa[j][2] *= al1; Oa[j][3] *= al1;
    }

#pragma unroll
    for (int kk = 0; kk < 4; kk++) {
      uint32_t paH[4] = {ph[kk*2][0], ph[kk*2][1], ph[kk*2+1][0], ph[kk*2+1][1]};
      uint32_t paL[4] = {pl[kk*2][0], pl[kk*2][1], pl[kk*2+1][0], pl[kk*2+1][1]};
#pragma unroll
      for (int dp = 0; dp < 8; dp++) {
        uint32_t bH[4], bL[4];
        const uint32_t voff =
            (uint32_t)(((kk << 4) + (lane & 7) + (((lane >> 3) & 1) << 3)) * ASTR
                       + (dp << 4) + ((lane >> 4) << 3)) * 2;
        ldsm4t(sVhi + voff, bH[0], bH[1], bH[2], bH[3]);
        ldsm4t(sVlo + voff, bL[0], bL[1], bL[2], bL[3]);
        mma16816(Oa[dp * 2],     paH, bH);
        mma16816(Oa[dp * 2],     paH, bL);
        mma16816(Oa[dp * 2],     paL, bH);
        mma16816(Oa[dp * 2 + 1], paH, bH + 2);
        mma16816(Oa[dp * 2 + 1], paH, bL + 2);
        mma16816(Oa[dp * 2 + 1], paL, bH + 2);
      }
    }

    __syncthreads();
    if (t + 2 < NT) issue_kv(t + 2);
  }

  l0 += __shfl_xor_sync(0xffffffffu, l0, 1);
  l0 += __shfl_xor_sync(0xffffffffu, l0, 2);
  l1 += __shfl_xor_sync(0xffffffffu, l1, 1);
  l1 += __shfl_xor_sync(0xffffffffu, l1, 2);
  const float inv0 = 1.f / l0;
  const float inv1 = 1.f / l1;
  const int row0 = q0 + warp_m + (lane >> 2);
  const int cofs = (lane & 3) << 1;
#pragma unroll
  for (int j = 0; j < 16; j++) {
    const int col = (j << 3) + cofs;
    float2 v0 = {Oa[j][0] * inv0, Oa[j][1] * inv0};
    float2 v1 = {Oa[j][2] * inv1, Oa[j][3] * inv1};
    *(float2*)&O[(bS + row0) * HID + h128 + col]     = v0;
    *(float2*)&O[(bS + row0 + 8) * HID + h128 + col] = v1;
  }
}

// ---------------------------------------------------------------------------
extern "C" void kernel_launch(void* const* d_in, const int* in_sizes, int n_in,
                              void* d_out, int out_size)
{
  (void)in_sizes; (void)n_in; (void)out_size;
  const float* x    = (const float*)d_in[0];
  const float* cosb = (const float*)d_in[1];
  const float* sinb = (const float*)d_in[2];
  const float* wq   = (const float*)d_in[3];
  const float* bq   = (const float*)d_in[4];
  const float* wk   = (const float*)d_in[5];
  const float* bk   = (const float*)d_in[6];
  const float* wv   = (const float*)d_in[7];
  const float* bv   = (const float*)d_in[8];
  const float* wo   = (const float*)d_in[9];
  float* out = (float*)d_out;

  float *q, *k, *v, *ao;
  cudaGetSymbolAddress((void**)&q,  g_q);
  cudaGetSymbolAddress((void**)&k,  g_k);
  cudaGetSymbolAddress((void**)&v,  g_v);
  cudaGetSymbolAddress((void**)&ao, g_ao);

  __nv_bfloat16 *qhi, *qlo, *khi, *klo, *vhi, *vlo;
  cudaGetSymbolAddress((void**)&qhi, g_qhi);
  cudaGetSymbolAddress((void**)&qlo, g_qlo);
  cudaGetSymbolAddress((void**)&khi, g_khi);
  cudaGetSymbolAddress((void**)&klo, g_klo);
  cudaGetSymbolAddress((void**)&vhi, g_vhi);
  cudaGetSymbolAddress((void**)&vlo, g_vlo);

  static bool attrs_set = false;
  if (!attrs_set) {
    cudaFuncSetAttribute(gemm_tf32,
                         cudaFuncAttributeMaxDynamicSharedMemorySize, GEMM_T_SMEM);
    cudaFuncSetAttribute(attn_mma,
                         cudaFuncAttributeMaxDynamicSharedMemorySize, A_SMEM);
    attrs_set = true;
  }

  const int NX = MROWS * HID;

  dim3 gg(HID / 128, MROWS / 128);  // (16, 32)
  gemm_tf32<<<gg, 256, GEMM_T_SMEM>>>(x,  wq, bq, q);
  gemm_tf32<<<gg, 256, GEMM_T_SMEM>>>(x,  wk, bk, k);
  gemm_tf32<<<gg, 256, GEMM_T_SMEM>>>(x,  wv, bv, v);

  rope_split<<<(MROWS * NH * 64) / 256, 256>>>(q, k, cosb, sinb, qhi, qlo, khi, klo);
  cvt_split<<<NX / 1024, 256>>>(v, vhi, vlo, NX);

  attn_mma<<<dim3(S_LEN / 128, BATCH * NH), 256, A_SMEM>>>(qhi, qlo, khi, klo, vhi, vlo, ao);

  gemm_tf32<<<gg, 256, GEMM_T_SMEM>>>(ao, wo, nullptr, out);
}